// round 14
// baseline (speedup 1.0000x reference)
#include <cuda_runtime.h>
#include <cuda_bf16.h>
#include <math.h>
#include <stdint.h>

#define BATCH 4096
#define NCLS 1000
#define DIM 512
#define QSZ 8192
#define INV_T (1.0f / 0.07f)
#define EPSP 1e-8f

// ---------------- scratch (__device__ globals; no allocations allowed) ------
__device__ __nv_bfloat16 g_featbf[BATCH * DIM];   // normalized embeddings (bf16)
__device__ __nv_bfloat16 g_centbf[NCLS * DIM];    // normalized centers (bf16)
__device__ __nv_bfloat16 g_qpbf[QSZ * DIM];       // label-permuted queue (bf16)
__device__ __nv_bfloat16 g_Sbf[(size_t)BATCH * QSZ];  // feat @ queue_p^T / T (bf16)
__device__ float g_CS[(size_t)BATCH * NCLS];      // feat @ cent^T / T
__device__ int   g_start[NCLS + 2];
__device__ int   g_perm[QSZ];
__device__ double g_acc[2];

// ---------------- row L2 normalize -> bf16 -----------------------------------
__global__ void norm_rows_bf(const float* __restrict__ x, __nv_bfloat16* __restrict__ y) {
    int r = blockIdx.x;
    const float4* xr = (const float4*)(x + (size_t)r * DIM);
    float4 v = xr[threadIdx.x];
    float ss = v.x * v.x + v.y * v.y + v.z * v.z + v.w * v.w;
#pragma unroll
    for (int o = 16; o; o >>= 1) ss += __shfl_down_sync(0xffffffffu, ss, o);
    __shared__ float sh[4];
    if ((threadIdx.x & 31) == 0) sh[threadIdx.x >> 5] = ss;
    __syncthreads();
    float tot = sh[0] + sh[1] + sh[2] + sh[3];
    float inv = 1.0f / fmaxf(sqrtf(tot), 1e-12f);
    __nv_bfloat162 lo = __floats2bfloat162_rn(v.x * inv, v.y * inv);
    __nv_bfloat162 hi = __floats2bfloat162_rn(v.z * inv, v.w * inv);
    __nv_bfloat162* yr = (__nv_bfloat162*)(y + (size_t)r * DIM);
    yr[threadIdx.x * 2 + 0] = lo;
    yr[threadIdx.x * 2 + 1] = hi;
}

// ---------------- counting sort of queue labels (single block) --------------
__global__ void build_perm(const int* __restrict__ labels) {
    __shared__ int cnt[NCLS + 1];
    __shared__ int cur[NCLS + 1];
    int tid = threadIdx.x;
    for (int i = tid; i < NCLS + 1; i += blockDim.x) cnt[i] = 0;
    if (tid == 0) { g_acc[0] = 0.0; g_acc[1] = 0.0; }
    __syncthreads();
    for (int q = tid; q < QSZ; q += blockDim.x) {
        int l = labels[q];
        int b = (l >= 0 && l < NCLS) ? l : NCLS;
        atomicAdd(&cnt[b], 1);
    }
    __syncthreads();
    if (tid == 0) {
        int run = 0;
        for (int c = 0; c < NCLS + 1; c++) {
            cur[c] = run;
            g_start[c] = run;
            run += cnt[c];
        }
        g_start[NCLS + 1] = run;
    }
    __syncthreads();
    for (int q = tid; q < QSZ; q += blockDim.x) {
        int l = labels[q];
        int b = (l >= 0 && l < NCLS) ? l : NCLS;
        int p = atomicAdd(&cur[b], 1);
        g_perm[p] = q;
    }
}

// ---------------- gather queue rows into label-sorted order (f32 -> bf16) ---
__global__ void permute_queue_bf(const float* __restrict__ queue) {
    int idx = blockIdx.x * blockDim.x + threadIdx.x;  // QSZ*128
    int r = idx >> 7, c = idx & 127;
    int src = g_perm[r];
    float4 v = ((const float4*)queue)[(size_t)src * 128 + c];
    __nv_bfloat162 lo = __floats2bfloat162_rn(v.x, v.y);
    __nv_bfloat162 hi = __floats2bfloat162_rn(v.z, v.w);
    __nv_bfloat162* yr = (__nv_bfloat162*)(g_qpbf + (size_t)r * DIM);
    yr[c * 2 + 0] = lo;
    yr[c * 2 + 1] = hi;
}

// ---------------- bf16 register tensor-core GEMM (big-tile cp.async) ---------
// C[m,n] = alpha * sum_k A[m,k]*B[n,k].  A:[M,K] bf16 rm, B:[N,K] bf16 rm.
// Output: f32 (BF16OUT=0) or bf16 (BF16OUT=1), row-major [M,N].
// Block 256x128x32, 8 warps (4 M x 2 N), warp tile 64x64.
// 2-stage cp.async double buffer (48 KB static smem exactly).
// SMEM tiles: [stage][rows][4 x 16B chunks], chunk swizzle c ^= (row>>1)&3.
#define TBM 256
#define TBN 128
#define TBK 32
#define A_STG (TBM * 64)   // 16384 B per stage
#define B_STG (TBN * 64)   // 8192 B per stage

__device__ __forceinline__ uint32_t smem_u32(const void* p) {
    uint32_t a;
    asm("{ .reg .u64 t; cvta.to.shared.u64 t, %1; cvt.u32.u64 %0, t; }"
        : "=r"(a) : "l"(p));
    return a;
}

__device__ __forceinline__ void mma_bf16(float c[4], const uint32_t a[4], const uint32_t b[2]) {
    asm volatile(
        "mma.sync.aligned.m16n8k16.row.col.f32.bf16.bf16.f32 "
        "{%0,%1,%2,%3}, {%4,%5,%6,%7}, {%8,%9}, {%0,%1,%2,%3};"
        : "+f"(c[0]), "+f"(c[1]), "+f"(c[2]), "+f"(c[3])
        : "r"(a[0]), "r"(a[1]), "r"(a[2]), "r"(a[3]), "r"(b[0]), "r"(b[1]));
}

__device__ __forceinline__ void ldsm4(uint32_t& r0, uint32_t& r1, uint32_t& r2, uint32_t& r3,
                                      uint32_t addr) {
    asm volatile("ldmatrix.sync.aligned.m8n8.x4.shared.b16 {%0,%1,%2,%3}, [%4];"
                 : "=r"(r0), "=r"(r1), "=r"(r2), "=r"(r3) : "r"(addr));
}

__device__ __forceinline__ void cpa16(uint32_t dst, const void* src, bool valid) {
    asm volatile("cp.async.cg.shared.global [%0], [%1], 16, %2;"
                 :: "r"(dst), "l"(src), "r"(valid ? 16 : 0));
}
#define CPA_COMMIT() asm volatile("cp.async.commit_group;" ::: "memory")
#define CPA_WAIT0()  asm volatile("cp.async.wait_group 0;" ::: "memory")

template <int BF16OUT>
__global__ __launch_bounds__(256, 1) void gemm_bf16(const __nv_bfloat16* __restrict__ A,
                                                    const __nv_bfloat16* __restrict__ Bm,
                                                    void* __restrict__ Cout,
                                                    int N, int K, float alpha) {
    __shared__ __align__(16) uint4 As4[2][TBM][4];   // 32 KB
    __shared__ __align__(16) uint4 Bs4[2][TBN][4];   // 16 KB
    int tid = threadIdx.x;
    int bx = blockIdx.x, by = blockIdx.y;
    int wid = tid >> 5, lane = tid & 31;
    int g = lane >> 2, t = lane & 3;
    int wm = (wid & 3) * 64;       // warp offset along M (4 warps)
    int wn = (wid >> 2) * 64;      // warp offset along N (2 warps)
    int m0 = tid >> 2;             // fill row 0..63
    int ch = tid & 3;              // fill 16B chunk

    int swc = ch ^ ((m0 >> 1) & 3);   // invariant under row += 64
    uint32_t Abase = smem_u32(As4);
    uint32_t Bbase = smem_u32(Bs4);
    uint32_t dA = Abase + ((uint32_t)m0 * 4 + swc) * 16;
    uint32_t dB = Bbase + ((uint32_t)m0 * 4 + swc) * 16;

    // ldmatrix per-lane invariants
    int l15 = lane & 15, hi = lane >> 4;
    int rowA = wm + l15;
    int rowB = wn + l15;

    float acc[4][8][4];
#pragma unroll
    for (int i = 0; i < 4; i++)
#pragma unroll
        for (int j = 0; j < 8; j++)
#pragma unroll
            for (int r = 0; r < 4; r++) acc[i][j][r] = 0.f;

    const __nv_bfloat16* Abasep = A + (size_t)(by * TBM) * K;
    int nrow0 = bx * TBN + m0;
    int nrow1 = nrow0 + 64;
    bool bv0 = nrow0 < N, bv1 = nrow1 < N;
    const __nv_bfloat16* srcA = Abasep + (size_t)m0 * K + ch * 8;   // rows +0,+64,+128,+192
    const __nv_bfloat16* srcB0 = Bm + (size_t)nrow0 * K + ch * 8;   // guarded by bv0
    const __nv_bfloat16* srcB1 = Bm + (size_t)nrow1 * K + ch * 8;   // guarded by bv1
    const size_t rstep = (size_t)64 * K;   // 64 rows in elements

    int ntiles = K / TBK;

    // prologue: issue stage 0 (tile 0)
    {
        cpa16(dA,                srcA, true);
        cpa16(dA + 64 * 64,      srcA + rstep, true);
        cpa16(dA + 128 * 64,     srcA + 2 * rstep, true);
        cpa16(dA + 192 * 64,     srcA + 3 * rstep, true);
        cpa16(dB,                srcB0, bv0);
        cpa16(dB + 64 * 64,      srcB1, bv1);
        CPA_COMMIT();
    }

    for (int kt = 0; kt < ntiles; kt++) {
        CPA_WAIT0();          // tile kt resident (this thread's part)
        __syncthreads();      // whole tile visible; all warps done with other buffer

        // prefetch tile kt+1 into buffer (kt+1)&1 (safe: everyone past compute kt-1)
        if (kt + 1 < ntiles) {
            uint32_t so = (uint32_t)((kt + 1) & 1);
            uint32_t soA = so * A_STG, soB = so * B_STG;
            int kc = (kt + 1) * TBK;
            cpa16(dA + soA,            srcA + kc, true);
            cpa16(dA + soA + 64 * 64,  srcA + rstep + kc, true);
            cpa16(dA + soA + 128 * 64, srcA + 2 * rstep + kc, true);
            cpa16(dA + soA + 192 * 64, srcA + 3 * rstep + kc, true);
            cpa16(dB + soB,            srcB0 + kc, bv0);
            cpa16(dB + soB + 64 * 64,  srcB1 + kc, bv1);
        }
        CPA_COMMIT();

        uint32_t Ab = Abase + (uint32_t)(kt & 1) * A_STG;
        uint32_t Bb = Bbase + (uint32_t)(kt & 1) * B_STG;
#pragma unroll
        for (int ks = 0; ks < 2; ks++) {
            int cb = ks * 2 + hi;
            uint32_t afr[4][4], bfr[8][2];
#pragma unroll
            for (int i = 0; i < 4; i++) {
                int r = rowA + i * 16;
                int c = cb ^ ((r >> 1) & 3);
                ldsm4(afr[i][0], afr[i][1], afr[i][2], afr[i][3],
                      Ab + (uint32_t)r * 64 + (uint32_t)c * 16);
            }
#pragma unroll
            for (int jj = 0; jj < 4; jj++) {
                int r = rowB + jj * 16;
                int c = cb ^ ((r >> 1) & 3);
                uint32_t q0, q1, q2, q3;
                ldsm4(q0, q1, q2, q3, Bb + (uint32_t)r * 64 + (uint32_t)c * 16);
                bfr[2 * jj][0] = q0;  bfr[2 * jj][1] = q2;
                bfr[2 * jj + 1][0] = q1;  bfr[2 * jj + 1][1] = q3;
            }
#pragma unroll
            for (int i = 0; i < 4; i++)
#pragma unroll
                for (int j = 0; j < 8; j++) mma_bf16(acc[i][j], afr[i], bfr[j]);
        }
    }

#pragma unroll
    for (int i = 0; i < 4; i++) {
        int row = by * TBM + wm + i * 16 + g;
#pragma unroll
        for (int j = 0; j < 8; j++) {
            int col = bx * TBN + wn + j * 8 + t * 2;
            if (BF16OUT) {
                __nv_bfloat16* Cm = (__nv_bfloat16*)Cout;
                if (col + 1 < N) {
                    __nv_bfloat162 v0 = __floats2bfloat162_rn(alpha * acc[i][j][0],
                                                              alpha * acc[i][j][1]);
                    __nv_bfloat162 v1 = __floats2bfloat162_rn(alpha * acc[i][j][2],
                                                              alpha * acc[i][j][3]);
                    *(__nv_bfloat162*)(Cm + (size_t)row * N + col) = v0;
                    *(__nv_bfloat162*)(Cm + (size_t)(row + 8) * N + col) = v1;
                } else if (col < N) {
                    Cm[(size_t)row * N + col] = __float2bfloat16(alpha * acc[i][j][0]);
                    Cm[(size_t)(row + 8) * N + col] = __float2bfloat16(alpha * acc[i][j][2]);
                }
            } else {
                float* Cm = (float*)Cout;
                if (col + 1 < N) {
                    float2 v0 = make_float2(alpha * acc[i][j][0], alpha * acc[i][j][1]);
                    float2 v1 = make_float2(alpha * acc[i][j][2], alpha * acc[i][j][3]);
                    *(float2*)(Cm + (size_t)row * N + col) = v0;
                    *(float2*)(Cm + (size_t)(row + 8) * N + col) = v1;
                } else if (col < N) {
                    Cm[(size_t)row * N + col] = alpha * acc[i][j][0];
                    Cm[(size_t)(row + 8) * N + col] = alpha * acc[i][j][2];
                }
            }
        }
    }
}

// ---------------- contrastive CE: one block per batch row, smem-staged S ----
__global__ __launch_bounds__(256) void row_contrastive(const float* __restrict__ prior,
                                                       const int* __restrict__ targets,
                                                       const unsigned char* __restrict__ init) {
    int b = blockIdx.x, tid = threadIdx.x;
    __shared__ __nv_bfloat16 sS[QSZ];          // 16 KB
    __shared__ float sm[256], ssum[256];
    __shared__ float stv;

    const uint4* src = (const uint4*)(g_Sbf + (size_t)b * QSZ);
    uint4* dst = (uint4*)sS;
#pragma unroll
    for (int i = 0; i < 4; i++) dst[tid + i * 256] = src[tid + i * 256];

    const float* CSrow = g_CS + (size_t)b * NCLS;
    int tgt = targets[b];
    __syncthreads();

    float m = -INFINITY, s = 0.f;
    for (int c = tid; c < NCLS; c += 256) {
        int s0 = g_start[c], s1 = g_start[c + 1];
        int cnt = s1 - s0;
        float ql = 0.f;
        if (cnt > 0) {
            float mx = -INFINITY;
            for (int q = s0; q < s1; q++) mx = fmaxf(mx, __bfloat162float(sS[q]));
            float se = 0.f;
            for (int q = s0; q < s1; q++) se += __expf(__bfloat162float(sS[q]) - mx);
            ql = mx + __logf(se) - __logf((float)cnt);
        }
        float cl = init[c] ? CSrow[c] : 0.f;
        float a = fmaxf(cl, ql), d = fminf(cl, ql);
        float comp = a + log1pf(__expf(d - a));
        float v = comp - logf(fmaxf(prior[c], EPSP));
        if (c == tgt) stv = v;
        if (v > m) { s = s * __expf(m - v) + 1.f; m = v; }
        else        { s += __expf(v - m); }
    }
    sm[tid] = m; ssum[tid] = s;
    __syncthreads();
    for (int o = 128; o; o >>= 1) {
        if (tid < o) {
            float m2 = sm[tid + o], s2 = ssum[tid + o];
            float M = fmaxf(sm[tid], m2);
            ssum[tid] = ssum[tid] * __expf(sm[tid] - M) + s2 * __expf(m2 - M);
            sm[tid] = M;
        }
        __syncthreads();
    }
    if (tid == 0) {
        float lse = sm[0] + __logf(ssum[0]);
        atomicAdd(&g_acc[1], (double)(lse - stv));
    }
}

// ---------------- plain classification CE -----------------------------------
__global__ __launch_bounds__(256) void row_cls(const float* __restrict__ logits,
                                               const float* __restrict__ prior,
                                               const int* __restrict__ targets) {
    int b = blockIdx.x, tid = threadIdx.x;
    const float* L = logits + (size_t)b * NCLS;
    int tgt = targets[b];
    __shared__ float sm[256], ssum[256];
    __shared__ float stv;
    float m = -INFINITY, s = 0.f;
    for (int c = tid; c < NCLS; c += 256) {
        float v = L[c] - logf(fmaxf(prior[c], EPSP));
        if (c == tgt) stv = v;
        if (v > m) { s = s * __expf(m - v) + 1.f; m = v; }
        else        { s += __expf(v - m); }
    }
    sm[tid] = m; ssum[tid] = s;
    __syncthreads();
    for (int o = 128; o; o >>= 1) {
        if (tid < o) {
            float m2 = sm[tid + o], s2 = ssum[tid + o];
            float M = fmaxf(sm[tid], m2);
            ssum[tid] = ssum[tid] * __expf(sm[tid] - M) + s2 * __expf(m2 - M);
            sm[tid] = M;
        }
        __syncthreads();
    }
    if (tid == 0) {
        float lse = sm[0] + __logf(ssum[0]);
        atomicAdd(&g_acc[0], (double)(lse - stv));
    }
}

__global__ void finalize(float* out) {
    out[0] = (float)(1.0 * (g_acc[0] / BATCH) + 0.1 * (g_acc[1] / BATCH));
}

// ---------------- launch ----------------------------------------------------
extern "C" void kernel_launch(void* const* d_in, const int* in_sizes, int n_in,
                              void* d_out, int out_size) {
    const float* logits    = (const float*)d_in[0];
    const float* embed     = (const float*)d_in[1];
    const float* centers   = (const float*)d_in[2];
    const float* queue     = (const float*)d_in[3];
    const float* prior     = (const float*)d_in[4];
    const int*   targets   = (const int*)d_in[5];
    const unsigned char* cinit = (const unsigned char*)d_in[6];
    const int*   qlabels   = (const int*)d_in[7];
    float* out = (float*)d_out;

    __nv_bfloat16* featbf; cudaGetSymbolAddress((void**)&featbf, g_featbf);
    __nv_bfloat16* centbf; cudaGetSymbolAddress((void**)&centbf, g_centbf);
    __nv_bfloat16* qpbf;   cudaGetSymbolAddress((void**)&qpbf,   g_qpbf);
    __nv_bfloat16* Sbf;    cudaGetSymbolAddress((void**)&Sbf,    g_Sbf);
    float* CS; cudaGetSymbolAddress((void**)&CS, g_CS);

    norm_rows_bf<<<BATCH, 128>>>(embed, featbf);
    norm_rows_bf<<<NCLS, 128>>>(centers, centbf);
    build_perm<<<1, 1024>>>(qlabels);
    permute_queue_bf<<<(QSZ * 128) / 256, 256>>>(queue);

    dim3 gS(QSZ / TBN, BATCH / TBM);
    gemm_bf16<1><<<gS, 256>>>(featbf, qpbf, Sbf, QSZ, DIM, INV_T);
    dim3 gC((NCLS + TBN - 1) / TBN, BATCH / TBM);
    gemm_bf16<0><<<gC, 256>>>(featbf, centbf, CS, NCLS, DIM, INV_T);

    row_contrastive<<<BATCH, 256>>>(prior, targets, cinit);
    row_cls<<<BATCH, 256>>>(logits, prior, targets);
    finalize<<<1, 1>>>(out);
}

// round 15
// speedup vs baseline: 1.1112x; 1.1112x over previous
#include <cuda_runtime.h>
#include <cuda_bf16.h>
#include <math.h>
#include <stdint.h>

#define BATCH 4096
#define NCLS 1000
#define DIM 512
#define QSZ 8192
#define INV_T (1.0f / 0.07f)
#define EPSP 1e-8f

// ---------------- scratch (__device__ globals; no allocations allowed) ------
__device__ __nv_bfloat16 g_featbf[BATCH * DIM];   // normalized embeddings (bf16)
__device__ __nv_bfloat16 g_centbf[NCLS * DIM];    // normalized centers (bf16)
__device__ __nv_bfloat16 g_qpbf[QSZ * DIM];       // label-permuted queue (bf16)
__device__ __nv_bfloat16 g_Sbf[(size_t)BATCH * QSZ];  // feat @ queue_p^T / T (bf16)
__device__ float g_CS[(size_t)BATCH * NCLS];      // feat @ cent^T / T
__device__ int   g_start[NCLS + 2];
__device__ int   g_perm[QSZ];
__device__ double g_acc[2];

// ---------------- row L2 normalize -> bf16 -----------------------------------
__global__ void norm_rows_bf(const float* __restrict__ x, __nv_bfloat16* __restrict__ y) {
    int r = blockIdx.x;
    const float4* xr = (const float4*)(x + (size_t)r * DIM);
    float4 v = xr[threadIdx.x];
    float ss = v.x * v.x + v.y * v.y + v.z * v.z + v.w * v.w;
#pragma unroll
    for (int o = 16; o; o >>= 1) ss += __shfl_down_sync(0xffffffffu, ss, o);
    __shared__ float sh[4];
    if ((threadIdx.x & 31) == 0) sh[threadIdx.x >> 5] = ss;
    __syncthreads();
    float tot = sh[0] + sh[1] + sh[2] + sh[3];
    float inv = 1.0f / fmaxf(sqrtf(tot), 1e-12f);
    __nv_bfloat162 lo = __floats2bfloat162_rn(v.x * inv, v.y * inv);
    __nv_bfloat162 hi = __floats2bfloat162_rn(v.z * inv, v.w * inv);
    __nv_bfloat162* yr = (__nv_bfloat162*)(y + (size_t)r * DIM);
    yr[threadIdx.x * 2 + 0] = lo;
    yr[threadIdx.x * 2 + 1] = hi;
}

// ---------------- counting sort of queue labels (single block) --------------
__global__ void build_perm(const int* __restrict__ labels) {
    __shared__ int cnt[NCLS + 1];
    __shared__ int cur[NCLS + 1];
    int tid = threadIdx.x;
    for (int i = tid; i < NCLS + 1; i += blockDim.x) cnt[i] = 0;
    if (tid == 0) { g_acc[0] = 0.0; g_acc[1] = 0.0; }
    __syncthreads();
    for (int q = tid; q < QSZ; q += blockDim.x) {
        int l = labels[q];
        int b = (l >= 0 && l < NCLS) ? l : NCLS;
        atomicAdd(&cnt[b], 1);
    }
    __syncthreads();
    if (tid == 0) {
        int run = 0;
        for (int c = 0; c < NCLS + 1; c++) {
            cur[c] = run;
            g_start[c] = run;
            run += cnt[c];
        }
        g_start[NCLS + 1] = run;
    }
    __syncthreads();
    for (int q = tid; q < QSZ; q += blockDim.x) {
        int l = labels[q];
        int b = (l >= 0 && l < NCLS) ? l : NCLS;
        int p = atomicAdd(&cur[b], 1);
        g_perm[p] = q;
    }
}

// ---------------- gather queue rows into label-sorted order (f32 -> bf16) ---
__global__ void permute_queue_bf(const float* __restrict__ queue) {
    int idx = blockIdx.x * blockDim.x + threadIdx.x;  // QSZ*128
    int r = idx >> 7, c = idx & 127;
    int src = g_perm[r];
    float4 v = ((const float4*)queue)[(size_t)src * 128 + c];
    __nv_bfloat162 lo = __floats2bfloat162_rn(v.x, v.y);
    __nv_bfloat162 hi = __floats2bfloat162_rn(v.z, v.w);
    __nv_bfloat162* yr = (__nv_bfloat162*)(g_qpbf + (size_t)r * DIM);
    yr[c * 2 + 0] = lo;
    yr[c * 2 + 1] = hi;
}

// ---------------- bf16 register tensor-core GEMM (cp.async 4-stage) ----------
// C[m,n] = alpha * sum_k A[m,k]*B[n,k].  A:[M,K] bf16 rm, B:[N,K] bf16 rm.
// Output: f32 (BF16OUT=0) or bf16 (BF16OUT=1), row-major [M,N].
// Block 128x128x32, 8 warps (4 M x 2 N), 4-stage cp.async pipeline,
// 64 KB dynamic smem, 2 CTAs/SM.
// SMEM tiles: [stage][128 rows][4 x 16B chunks], chunk swizzle c ^= (row>>1)&3.
#define TBM 128
#define TBN 128
#define TBK 32
#define NSTG 4
#define STG_BYTES (TBM * 64)            // 8192 per matrix per stage
#define A_TOTAL (NSTG * STG_BYTES)      // 32768
#define SMEM_GEMM (2 * A_TOTAL)         // 65536

__device__ __forceinline__ uint32_t smem_u32(const void* p) {
    uint32_t a;
    asm("{ .reg .u64 t; cvta.to.shared.u64 t, %1; cvt.u32.u64 %0, t; }"
        : "=r"(a) : "l"(p));
    return a;
}

__device__ __forceinline__ void mma_bf16(float c[4], const uint32_t a[4], const uint32_t b[2]) {
    asm volatile(
        "mma.sync.aligned.m16n8k16.row.col.f32.bf16.bf16.f32 "
        "{%0,%1,%2,%3}, {%4,%5,%6,%7}, {%8,%9}, {%0,%1,%2,%3};"
        : "+f"(c[0]), "+f"(c[1]), "+f"(c[2]), "+f"(c[3])
        : "r"(a[0]), "r"(a[1]), "r"(a[2]), "r"(a[3]), "r"(b[0]), "r"(b[1]));
}

__device__ __forceinline__ void ldsm4(uint32_t& r0, uint32_t& r1, uint32_t& r2, uint32_t& r3,
                                      uint32_t addr) {
    asm volatile("ldmatrix.sync.aligned.m8n8.x4.shared.b16 {%0,%1,%2,%3}, [%4];"
                 : "=r"(r0), "=r"(r1), "=r"(r2), "=r"(r3) : "r"(addr));
}

__device__ __forceinline__ void cpa16(uint32_t dst, const void* src, bool valid) {
    asm volatile("cp.async.cg.shared.global [%0], [%1], 16, %2;"
                 :: "r"(dst), "l"(src), "r"(valid ? 16 : 0));
}
#define CPA_COMMIT() asm volatile("cp.async.commit_group;" ::: "memory")
#define CPA_WAIT2()  asm volatile("cp.async.wait_group 2;" ::: "memory")

template <int BF16OUT>
__global__ __launch_bounds__(256, 2) void gemm_bf16(const __nv_bfloat16* __restrict__ A,
                                                    const __nv_bfloat16* __restrict__ Bm,
                                                    void* __restrict__ Cout,
                                                    int N, int K, float alpha) {
    extern __shared__ __align__(16) char dsm[];
    int tid = threadIdx.x;
    int bx = blockIdx.x, by = blockIdx.y;
    int wid = tid >> 5, lane = tid & 31;
    int g = lane >> 2, t = lane & 3;
    int wm = (wid & 3) * 32;       // warp offset along M
    int wn = (wid >> 2) * 64;      // warp offset along N
    int m0 = tid >> 2;             // fill row 0..63
    int ch = tid & 3;              // fill 16B chunk

    int swc = ch ^ ((m0 >> 1) & 3);
    uint32_t Abase = smem_u32(dsm);
    uint32_t Bbase = Abase + A_TOTAL;
    uint32_t dA0 = Abase + ((uint32_t)m0 * 4 + swc) * 16;
    uint32_t dA1 = dA0 + 64 * 64;
    uint32_t dB0 = Bbase + ((uint32_t)m0 * 4 + swc) * 16;
    uint32_t dB1 = dB0 + 64 * 64;

    int l15 = lane & 15, hi = lane >> 4;
    int rowA = wm + l15;
    int rowB = wn + l15;

    float acc[2][8][4];
#pragma unroll
    for (int i = 0; i < 2; i++)
#pragma unroll
        for (int j = 0; j < 8; j++)
#pragma unroll
            for (int r = 0; r < 4; r++) acc[i][j][r] = 0.f;

    const __nv_bfloat16* Abasep = A + (size_t)(by * TBM) * K;
    int nrow0 = bx * TBN + m0;
    int nrow1 = nrow0 + 64;
    bool bv0 = nrow0 < N, bv1 = nrow1 < N;
    const __nv_bfloat16* srcA0 = Abasep + (size_t)m0 * K + ch * 8;
    const __nv_bfloat16* srcA1 = Abasep + (size_t)(m0 + 64) * K + ch * 8;
    const __nv_bfloat16* srcB0 = Bm + (size_t)nrow0 * K + ch * 8;   // guarded by bv0
    const __nv_bfloat16* srcB1 = Bm + (size_t)nrow1 * K + ch * 8;   // guarded by bv1

    int ntiles = K / TBK;

    // prologue: issue stages 0..2
#pragma unroll
    for (int s = 0; s < NSTG - 1; s++) {
        uint32_t so = (uint32_t)s * STG_BYTES;
        int kc = s * TBK;
        cpa16(dA0 + so, srcA0 + kc, true);
        cpa16(dA1 + so, srcA1 + kc, true);
        cpa16(dB0 + so, srcB0 + kc, bv0);
        cpa16(dB1 + so, srcB1 + kc, bv1);
        CPA_COMMIT();
    }

    int stg = 0;          // stage holding tile kt
    int wstg = NSTG - 1;  // stage to write next prefetch into
    for (int kt = 0; kt < ntiles; kt++) {
        CPA_WAIT2();          // tile kt resident (this thread's part)
        __syncthreads();      // whole tile visible; all warps done with buf wstg

        // prefetch tile kt+3 into wstg (buffer consumed at iter kt-1)
        if (kt + NSTG - 1 < ntiles) {
            uint32_t so = (uint32_t)wstg * STG_BYTES;
            int kc = (kt + NSTG - 1) * TBK;
            cpa16(dA0 + so, srcA0 + kc, true);
            cpa16(dA1 + so, srcA1 + kc, true);
            cpa16(dB0 + so, srcB0 + kc, bv0);
            cpa16(dB1 + so, srcB1 + kc, bv1);
        }
        CPA_COMMIT();         // always commit (empty group in tail)

        uint32_t Ab = Abase + (uint32_t)stg * STG_BYTES;
        uint32_t Bb = Bbase + (uint32_t)stg * STG_BYTES;
#pragma unroll
        for (int ks = 0; ks < 2; ks++) {
            int cb = ks * 2 + hi;
            uint32_t afr[2][4], bfr[8][2];
#pragma unroll
            for (int i = 0; i < 2; i++) {
                int r = rowA + i * 16;
                int c = cb ^ ((r >> 1) & 3);
                ldsm4(afr[i][0], afr[i][1], afr[i][2], afr[i][3],
                      Ab + (uint32_t)r * 64 + (uint32_t)c * 16);
            }
#pragma unroll
            for (int jj = 0; jj < 4; jj++) {
                int r = rowB + jj * 16;
                int c = cb ^ ((r >> 1) & 3);
                uint32_t q0, q1, q2, q3;
                ldsm4(q0, q1, q2, q3, Bb + (uint32_t)r * 64 + (uint32_t)c * 16);
                bfr[2 * jj][0] = q0;  bfr[2 * jj][1] = q2;
                bfr[2 * jj + 1][0] = q1;  bfr[2 * jj + 1][1] = q3;
            }
#pragma unroll
            for (int i = 0; i < 2; i++)
#pragma unroll
                for (int j = 0; j < 8; j++) mma_bf16(acc[i][j], afr[i], bfr[j]);
        }
        stg = (stg + 1) & (NSTG - 1);
        wstg = (wstg + 1) & (NSTG - 1);
    }

#pragma unroll
    for (int i = 0; i < 2; i++) {
        int row = by * TBM + wm + i * 16 + g;
#pragma unroll
        for (int j = 0; j < 8; j++) {
            int col = bx * TBN + wn + j * 8 + t * 2;
            if (BF16OUT) {
                __nv_bfloat16* Cm = (__nv_bfloat16*)Cout;
                if (col + 1 < N) {
                    __nv_bfloat162 v0 = __floats2bfloat162_rn(alpha * acc[i][j][0],
                                                              alpha * acc[i][j][1]);
                    __nv_bfloat162 v1 = __floats2bfloat162_rn(alpha * acc[i][j][2],
                                                              alpha * acc[i][j][3]);
                    *(__nv_bfloat162*)(Cm + (size_t)row * N + col) = v0;
                    *(__nv_bfloat162*)(Cm + (size_t)(row + 8) * N + col) = v1;
                } else if (col < N) {
                    Cm[(size_t)row * N + col] = __float2bfloat16(alpha * acc[i][j][0]);
                    Cm[(size_t)(row + 8) * N + col] = __float2bfloat16(alpha * acc[i][j][2]);
                }
            } else {
                float* Cm = (float*)Cout;
                if (col + 1 < N) {
                    float2 v0 = make_float2(alpha * acc[i][j][0], alpha * acc[i][j][1]);
                    float2 v1 = make_float2(alpha * acc[i][j][2], alpha * acc[i][j][3]);
                    *(float2*)(Cm + (size_t)row * N + col) = v0;
                    *(float2*)(Cm + (size_t)(row + 8) * N + col) = v1;
                } else if (col < N) {
                    Cm[(size_t)row * N + col] = alpha * acc[i][j][0];
                    Cm[(size_t)(row + 8) * N + col] = alpha * acc[i][j][2];
                }
            }
        }
    }
}

// ---------------- fused CE: both loss terms, one block per batch row ---------
__global__ __launch_bounds__(256) void row_both(const float* __restrict__ logits,
                                                const float* __restrict__ prior,
                                                const int* __restrict__ targets,
                                                const unsigned char* __restrict__ init) {
    int b = blockIdx.x, tid = threadIdx.x;
    __shared__ __nv_bfloat16 sS[QSZ];          // 16 KB
    __shared__ float sm1[256], ss1[256], sm2[256], ss2[256];
    __shared__ float stv1, stv2;

    const uint4* src = (const uint4*)(g_Sbf + (size_t)b * QSZ);
    uint4* dst = (uint4*)sS;
#pragma unroll
    for (int i = 0; i < 4; i++) dst[tid + i * 256] = src[tid + i * 256];

    const float* CSrow = g_CS + (size_t)b * NCLS;
    const float* Lrow = logits + (size_t)b * NCLS;
    int tgt = targets[b];
    __syncthreads();

    float m1 = -INFINITY, s1 = 0.f;   // contrastive
    float m2 = -INFINITY, s2 = 0.f;   // cls
    for (int c = tid; c < NCLS; c += 256) {
        float pa = logf(fmaxf(prior[c], EPSP));
        // contrastive logit
        int q0 = g_start[c], q1 = g_start[c + 1];
        int cnt = q1 - q0;
        float ql = 0.f;
        if (cnt > 0) {
            float mx = -INFINITY;
            for (int q = q0; q < q1; q++) mx = fmaxf(mx, __bfloat162float(sS[q]));
            float se = 0.f;
            for (int q = q0; q < q1; q++) se += __expf(__bfloat162float(sS[q]) - mx);
            ql = mx + __logf(se) - __logf((float)cnt);
        }
        float cl = init[c] ? CSrow[c] : 0.f;
        float a = fmaxf(cl, ql), d = fminf(cl, ql);
        float v1 = a + log1pf(__expf(d - a)) - pa;
        // cls logit
        float v2 = Lrow[c] - pa;
        if (c == tgt) { stv1 = v1; stv2 = v2; }
        if (v1 > m1) { s1 = s1 * __expf(m1 - v1) + 1.f; m1 = v1; }
        else          { s1 += __expf(v1 - m1); }
        if (v2 > m2) { s2 = s2 * __expf(m2 - v2) + 1.f; m2 = v2; }
        else          { s2 += __expf(v2 - m2); }
    }
    sm1[tid] = m1; ss1[tid] = s1;
    sm2[tid] = m2; ss2[tid] = s2;
    __syncthreads();
    for (int o = 128; o; o >>= 1) {
        if (tid < o) {
            float ma = sm1[tid + o], sa = ss1[tid + o];
            float M = fmaxf(sm1[tid], ma);
            ss1[tid] = ss1[tid] * __expf(sm1[tid] - M) + sa * __expf(ma - M);
            sm1[tid] = M;
            float mb = sm2[tid + o], sb = ss2[tid + o];
            float M2 = fmaxf(sm2[tid], mb);
            ss2[tid] = ss2[tid] * __expf(sm2[tid] - M2) + sb * __expf(mb - M2);
            sm2[tid] = M2;
        }
        __syncthreads();
    }
    if (tid == 0) {
        float lse1 = sm1[0] + __logf(ss1[0]);
        float lse2 = sm2[0] + __logf(ss2[0]);
        atomicAdd(&g_acc[1], (double)(lse1 - stv1));
        atomicAdd(&g_acc[0], (double)(lse2 - stv2));
    }
}

__global__ void finalize(float* out) {
    out[0] = (float)(1.0 * (g_acc[0] / BATCH) + 0.1 * (g_acc[1] / BATCH));
}

// ---------------- launch ----------------------------------------------------
extern "C" void kernel_launch(void* const* d_in, const int* in_sizes, int n_in,
                              void* d_out, int out_size) {
    const float* logits    = (const float*)d_in[0];
    const float* embed     = (const float*)d_in[1];
    const float* centers   = (const float*)d_in[2];
    const float* queue     = (const float*)d_in[3];
    const float* prior     = (const float*)d_in[4];
    const int*   targets   = (const int*)d_in[5];
    const unsigned char* cinit = (const unsigned char*)d_in[6];
    const int*   qlabels   = (const int*)d_in[7];
    float* out = (float*)d_out;

    __nv_bfloat16* featbf; cudaGetSymbolAddress((void**)&featbf, g_featbf);
    __nv_bfloat16* centbf; cudaGetSymbolAddress((void**)&centbf, g_centbf);
    __nv_bfloat16* qpbf;   cudaGetSymbolAddress((void**)&qpbf,   g_qpbf);
    __nv_bfloat16* Sbf;    cudaGetSymbolAddress((void**)&Sbf,    g_Sbf);
    float* CS; cudaGetSymbolAddress((void**)&CS, g_CS);

    cudaFuncSetAttribute(gemm_bf16<1>, cudaFuncAttributeMaxDynamicSharedMemorySize, SMEM_GEMM);
    cudaFuncSetAttribute(gemm_bf16<0>, cudaFuncAttributeMaxDynamicSharedMemorySize, SMEM_GEMM);

    norm_rows_bf<<<BATCH, 128>>>(embed, featbf);
    norm_rows_bf<<<NCLS, 128>>>(centers, centbf);
    build_perm<<<1, 1024>>>(qlabels);
    permute_queue_bf<<<(QSZ * 128) / 256, 256>>>(queue);

    dim3 gS(QSZ / TBN, BATCH / TBM);
    gemm_bf16<1><<<gS, 256, SMEM_GEMM>>>(featbf, qpbf, Sbf, QSZ, DIM, INV_T);
    dim3 gC((NCLS + TBN - 1) / TBN, BATCH / TBM);
    gemm_bf16<0><<<gC, 256, SMEM_GEMM>>>(featbf, centbf, CS, NCLS, DIM, INV_T);

    row_both<<<BATCH, 256>>>(logits, prior, targets, cinit);
    finalize<<<1, 1>>>(out);
}

// round 16
// speedup vs baseline: 1.1503x; 1.0353x over previous
#include <cuda_runtime.h>
#include <cuda_bf16.h>
#include <math.h>
#include <stdint.h>

#define BATCH 4096
#define NCLS 1000
#define DIM 512
#define QSZ 8192
#define INV_T (1.0f / 0.07f)
#define EPSP 1e-8f

// ---------------- scratch (__device__ globals; no allocations allowed) ------
__device__ __nv_bfloat16 g_featbf[BATCH * DIM];   // normalized embeddings (bf16)
__device__ __nv_bfloat16 g_centbf[NCLS * DIM];    // normalized centers (bf16)
__device__ __nv_bfloat16 g_qpbf[QSZ * DIM];       // label-permuted queue (bf16)
__device__ __nv_bfloat16 g_Sbf[(size_t)BATCH * QSZ];  // feat @ queue_p^T / T (bf16)
__device__ float g_CS[(size_t)BATCH * NCLS];      // feat @ cent^T / T
__device__ int   g_start[NCLS + 2];
__device__ int   g_perm[QSZ];
__device__ double g_acc[2];

// ---------------- row L2 normalize -> bf16 -----------------------------------
__global__ void norm_rows_bf(const float* __restrict__ x, __nv_bfloat16* __restrict__ y) {
    int r = blockIdx.x;
    const float4* xr = (const float4*)(x + (size_t)r * DIM);
    float4 v = xr[threadIdx.x];
    float ss = v.x * v.x + v.y * v.y + v.z * v.z + v.w * v.w;
#pragma unroll
    for (int o = 16; o; o >>= 1) ss += __shfl_down_sync(0xffffffffu, ss, o);
    __shared__ float sh[4];
    if ((threadIdx.x & 31) == 0) sh[threadIdx.x >> 5] = ss;
    __syncthreads();
    float tot = sh[0] + sh[1] + sh[2] + sh[3];
    float inv = 1.0f / fmaxf(sqrtf(tot), 1e-12f);
    __nv_bfloat162 lo = __floats2bfloat162_rn(v.x * inv, v.y * inv);
    __nv_bfloat162 hi = __floats2bfloat162_rn(v.z * inv, v.w * inv);
    __nv_bfloat162* yr = (__nv_bfloat162*)(y + (size_t)r * DIM);
    yr[threadIdx.x * 2 + 0] = lo;
    yr[threadIdx.x * 2 + 1] = hi;
}

// ---------------- counting sort of queue labels (single block) --------------
__global__ void build_perm(const int* __restrict__ labels) {
    __shared__ int cnt[NCLS + 1];
    __shared__ int cur[NCLS + 1];
    int tid = threadIdx.x;
    for (int i = tid; i < NCLS + 1; i += blockDim.x) cnt[i] = 0;
    if (tid == 0) { g_acc[0] = 0.0; g_acc[1] = 0.0; }
    __syncthreads();
    for (int q = tid; q < QSZ; q += blockDim.x) {
        int l = labels[q];
        int b = (l >= 0 && l < NCLS) ? l : NCLS;
        atomicAdd(&cnt[b], 1);
    }
    __syncthreads();
    if (tid == 0) {
        int run = 0;
        for (int c = 0; c < NCLS + 1; c++) {
            cur[c] = run;
            g_start[c] = run;
            run += cnt[c];
        }
        g_start[NCLS + 1] = run;
    }
    __syncthreads();
    for (int q = tid; q < QSZ; q += blockDim.x) {
        int l = labels[q];
        int b = (l >= 0 && l < NCLS) ? l : NCLS;
        int p = atomicAdd(&cur[b], 1);
        g_perm[p] = q;
    }
}

// ---------------- gather queue rows into label-sorted order (f32 -> bf16) ---
__global__ void permute_queue_bf(const float* __restrict__ queue) {
    int idx = blockIdx.x * blockDim.x + threadIdx.x;  // QSZ*128
    int r = idx >> 7, c = idx & 127;
    int src = g_perm[r];
    float4 v = ((const float4*)queue)[(size_t)src * 128 + c];
    __nv_bfloat162 lo = __floats2bfloat162_rn(v.x, v.y);
    __nv_bfloat162 hi = __floats2bfloat162_rn(v.z, v.w);
    __nv_bfloat162* yr = (__nv_bfloat162*)(g_qpbf + (size_t)r * DIM);
    yr[c * 2 + 0] = lo;
    yr[c * 2 + 1] = hi;
}

// ---------------- merged bf16 tensor-core GEMM (k64 tiles, 3-stage) ----------
// bx < QTILES: S = feat @ qp^T * INV_T   -> bf16 out [BATCH, QSZ]
// else:        CS = feat @ cent^T * INV_T -> f32 out [BATCH, NCLS] (guarded)
// Block 128x128x64, 8 warps (4 M x 2 N), 3-stage cp.async, 96 KB dyn smem.
// SMEM tile rows are 128 B (8 x 16B chunks); swizzle: chunk ^= (row & 7).
#define TBM 128
#define TBN 128
#define TBK 64
#define NSTG 3
#define QTILES (QSZ / TBN)              // 64
#define CTILES ((NCLS + TBN - 1) / TBN) // 8
#define STG_BYTES (TBM * 128)           // 16384 per matrix per stage
#define A_TOTAL (NSTG * STG_BYTES)      // 49152
#define SMEM_GEMM (2 * A_TOTAL)         // 98304

__device__ __forceinline__ uint32_t smem_u32(const void* p) {
    uint32_t a;
    asm("{ .reg .u64 t; cvta.to.shared.u64 t, %1; cvt.u32.u64 %0, t; }"
        : "=r"(a) : "l"(p));
    return a;
}

__device__ __forceinline__ void mma_bf16(float c[4], const uint32_t a[4], const uint32_t b[2]) {
    asm volatile(
        "mma.sync.aligned.m16n8k16.row.col.f32.bf16.bf16.f32 "
        "{%0,%1,%2,%3}, {%4,%5,%6,%7}, {%8,%9}, {%0,%1,%2,%3};"
        : "+f"(c[0]), "+f"(c[1]), "+f"(c[2]), "+f"(c[3])
        : "r"(a[0]), "r"(a[1]), "r"(a[2]), "r"(a[3]), "r"(b[0]), "r"(b[1]));
}

__device__ __forceinline__ void ldsm4(uint32_t& r0, uint32_t& r1, uint32_t& r2, uint32_t& r3,
                                      uint32_t addr) {
    asm volatile("ldmatrix.sync.aligned.m8n8.x4.shared.b16 {%0,%1,%2,%3}, [%4];"
                 : "=r"(r0), "=r"(r1), "=r"(r2), "=r"(r3) : "r"(addr));
}

__device__ __forceinline__ void cpa16(uint32_t dst, const void* src, bool valid) {
    asm volatile("cp.async.cg.shared.global [%0], [%1], 16, %2;"
                 :: "r"(dst), "l"(src), "r"(valid ? 16 : 0));
}
#define CPA_COMMIT() asm volatile("cp.async.commit_group;" ::: "memory")
#define CPA_WAIT1()  asm volatile("cp.async.wait_group 1;" ::: "memory")

__global__ __launch_bounds__(256, 2) void gemm_dual(const __nv_bfloat16* __restrict__ A,
                                                    const __nv_bfloat16* __restrict__ Bq,
                                                    const __nv_bfloat16* __restrict__ Bc,
                                                    __nv_bfloat16* __restrict__ Sout,
                                                    float* __restrict__ Cout) {
    extern __shared__ __align__(16) char dsm[];
    int tid = threadIdx.x;
    int bx = blockIdx.x, by = blockIdx.y;
    const float alpha = INV_T;
    const int K = DIM;

    bool isq = bx < QTILES;
    const __nv_bfloat16* Bm = isq ? Bq : Bc;
    int bxl = isq ? bx : bx - QTILES;
    int N = isq ? QSZ : NCLS;

    int wid = tid >> 5, lane = tid & 31;
    int g = lane >> 2, t = lane & 3;
    int wm = (wid & 3) * 32;       // warp offset along M
    int wn = (wid >> 2) * 64;      // warp offset along N

    // fill mapping: row r0 (+32p), 16B chunk ch8
    int r0 = tid >> 3;             // 0..31
    int ch8 = tid & 7;             // 0..7
    int sc = ch8 ^ (r0 & 7);       // swizzle (invariant under r0 += 32)
    uint32_t dOff = ((uint32_t)r0 * 8 + sc) * 16;

    uint32_t Abase = smem_u32(dsm);
    uint32_t Bbase = Abase + A_TOTAL;

    // ldmatrix per-lane invariants
    int l15 = lane & 15, hi = lane >> 4;
    int rowA = wm + l15;
    int rowB = wn + l15;

    float acc[2][8][4];
#pragma unroll
    for (int i = 0; i < 2; i++)
#pragma unroll
        for (int j = 0; j < 8; j++)
#pragma unroll
            for (int r = 0; r < 4; r++) acc[i][j][r] = 0.f;

    const __nv_bfloat16* srcA = A + (size_t)(by * TBM + r0) * K + ch8 * 8;
    int nrowb = bxl * TBN + r0;
    const __nv_bfloat16* srcB = Bm + (size_t)nrowb * K + ch8 * 8;
    bool bv[4];
#pragma unroll
    for (int p = 0; p < 4; p++) bv[p] = (nrowb + 32 * p) < N;
    const size_t rstep = (size_t)32 * K;

    const int ntiles = K / TBK;   // 8

    // prologue: issue stages 0..1
#pragma unroll
    for (int s = 0; s < NSTG - 1; s++) {
        uint32_t so = (uint32_t)s * STG_BYTES;
        int kc = s * TBK;
#pragma unroll
        for (int p = 0; p < 4; p++) {
            cpa16(Abase + so + dOff + p * 4096, srcA + p * rstep + kc, true);
            cpa16(Bbase + so + dOff + p * 4096, srcB + p * rstep + kc, bv[p]);
        }
        CPA_COMMIT();
    }

    int stg = 0, wstg = NSTG - 1;
    for (int kt = 0; kt < ntiles; kt++) {
        CPA_WAIT1();          // tile kt resident (this thread's part)
        __syncthreads();      // whole tile visible; all warps done with buf wstg

        if (kt + NSTG - 1 < ntiles) {
            uint32_t so = (uint32_t)wstg * STG_BYTES;
            int kc = (kt + NSTG - 1) * TBK;
#pragma unroll
            for (int p = 0; p < 4; p++) {
                cpa16(Abase + so + dOff + p * 4096, srcA + p * rstep + kc, true);
                cpa16(Bbase + so + dOff + p * 4096, srcB + p * rstep + kc, bv[p]);
            }
        }
        CPA_COMMIT();         // always commit (empty group in tail)

        uint32_t Ab = Abase + (uint32_t)stg * STG_BYTES;
        uint32_t Bb = Bbase + (uint32_t)stg * STG_BYTES;
#pragma unroll
        for (int ks = 0; ks < 4; ks++) {
            int cb = ks * 2 + hi;   // chunk before swizzle (0..7)
            uint32_t afr[2][4], bfr[8][2];
#pragma unroll
            for (int i = 0; i < 2; i++) {
                int r = rowA + i * 16;
                int c = cb ^ (r & 7);
                ldsm4(afr[i][0], afr[i][1], afr[i][2], afr[i][3],
                      Ab + (uint32_t)r * 128 + (uint32_t)c * 16);
            }
#pragma unroll
            for (int jj = 0; jj < 4; jj++) {
                int r = rowB + jj * 16;
                int c = cb ^ (r & 7);
                uint32_t q0, q1, q2, q3;
                ldsm4(q0, q1, q2, q3, Bb + (uint32_t)r * 128 + (uint32_t)c * 16);
                bfr[2 * jj][0] = q0;  bfr[2 * jj][1] = q2;
                bfr[2 * jj + 1][0] = q1;  bfr[2 * jj + 1][1] = q3;
            }
#pragma unroll
            for (int i = 0; i < 2; i++)
#pragma unroll
                for (int j = 0; j < 8; j++) mma_bf16(acc[i][j], afr[i], bfr[j]);
        }
        stg = stg + 1; if (stg == NSTG) stg = 0;
        wstg = wstg + 1; if (wstg == NSTG) wstg = 0;
    }

#pragma unroll
    for (int i = 0; i < 2; i++) {
        int row = by * TBM + wm + i * 16 + g;
#pragma unroll
        for (int j = 0; j < 8; j++) {
            int col = bxl * TBN + wn + j * 8 + t * 2;
            if (isq) {
                __nv_bfloat162 v0 = __floats2bfloat162_rn(alpha * acc[i][j][0],
                                                          alpha * acc[i][j][1]);
                __nv_bfloat162 v1 = __floats2bfloat162_rn(alpha * acc[i][j][2],
                                                          alpha * acc[i][j][3]);
                *(__nv_bfloat162*)(Sout + (size_t)row * QSZ + col) = v0;
                *(__nv_bfloat162*)(Sout + (size_t)(row + 8) * QSZ + col) = v1;
            } else {
                if (col + 1 < NCLS) {
                    float2 v0 = make_float2(alpha * acc[i][j][0], alpha * acc[i][j][1]);
                    float2 v1 = make_float2(alpha * acc[i][j][2], alpha * acc[i][j][3]);
                    *(float2*)(Cout + (size_t)row * NCLS + col) = v0;
                    *(float2*)(Cout + (size_t)(row + 8) * NCLS + col) = v1;
                } else if (col < NCLS) {
                    Cout[(size_t)row * NCLS + col] = alpha * acc[i][j][0];
                    Cout[(size_t)(row + 8) * NCLS + col] = alpha * acc[i][j][2];
                }
            }
        }
    }
}

// ---------------- fused CE: both loss terms, one block per batch row ---------
__global__ __launch_bounds__(256) void row_both(const float* __restrict__ logits,
                                                const float* __restrict__ prior,
                                                const int* __restrict__ targets,
                                                const unsigned char* __restrict__ init) {
    int b = blockIdx.x, tid = threadIdx.x;
    __shared__ __nv_bfloat16 sS[QSZ];          // 16 KB
    __shared__ float sm1[256], ss1[256], sm2[256], ss2[256];
    __shared__ float stv1, stv2;

    const uint4* src = (const uint4*)(g_Sbf + (size_t)b * QSZ);
    uint4* dst = (uint4*)sS;
#pragma unroll
    for (int i = 0; i < 4; i++) dst[tid + i * 256] = src[tid + i * 256];

    const float* CSrow = g_CS + (size_t)b * NCLS;
    const float* Lrow = logits + (size_t)b * NCLS;
    int tgt = targets[b];
    __syncthreads();

    float m1 = -INFINITY, s1 = 0.f;   // contrastive
    float m2 = -INFINITY, s2 = 0.f;   // cls
    for (int c = tid; c < NCLS; c += 256) {
        float pa = logf(fmaxf(prior[c], EPSP));
        int q0 = g_start[c], q1 = g_start[c + 1];
        int cnt = q1 - q0;
        float ql = 0.f;
        if (cnt > 0) {
            float mx = -INFINITY;
            for (int q = q0; q < q1; q++) mx = fmaxf(mx, __bfloat162float(sS[q]));
            float se = 0.f;
            for (int q = q0; q < q1; q++) se += __expf(__bfloat162float(sS[q]) - mx);
            ql = mx + __logf(se) - __logf((float)cnt);
        }
        float cl = init[c] ? CSrow[c] : 0.f;
        float a = fmaxf(cl, ql), d = fminf(cl, ql);
        float v1 = a + log1pf(__expf(d - a)) - pa;
        float v2 = Lrow[c] - pa;
        if (c == tgt) { stv1 = v1; stv2 = v2; }
        if (v1 > m1) { s1 = s1 * __expf(m1 - v1) + 1.f; m1 = v1; }
        else          { s1 += __expf(v1 - m1); }
        if (v2 > m2) { s2 = s2 * __expf(m2 - v2) + 1.f; m2 = v2; }
        else          { s2 += __expf(v2 - m2); }
    }
    sm1[tid] = m1; ss1[tid] = s1;
    sm2[tid] = m2; ss2[tid] = s2;
    __syncthreads();
    for (int o = 128; o; o >>= 1) {
        if (tid < o) {
            float ma = sm1[tid + o], sa = ss1[tid + o];
            float M = fmaxf(sm1[tid], ma);
            ss1[tid] = ss1[tid] * __expf(sm1[tid] - M) + sa * __expf(ma - M);
            sm1[tid] = M;
            float mb = sm2[tid + o], sb = ss2[tid + o];
            float M2 = fmaxf(sm2[tid], mb);
            ss2[tid] = ss2[tid] * __expf(sm2[tid] - M2) + sb * __expf(mb - M2);
            sm2[tid] = M2;
        }
        __syncthreads();
    }
    if (tid == 0) {
        float lse1 = sm1[0] + __logf(ss1[0]);
        float lse2 = sm2[0] + __logf(ss2[0]);
        atomicAdd(&g_acc[1], (double)(lse1 - stv1));
        atomicAdd(&g_acc[0], (double)(lse2 - stv2));
    }
}

__global__ void finalize(float* out) {
    out[0] = (float)(1.0 * (g_acc[0] / BATCH) + 0.1 * (g_acc[1] / BATCH));
}

// ---------------- launch ----------------------------------------------------
extern "C" void kernel_launch(void* const* d_in, const int* in_sizes, int n_in,
                              void* d_out, int out_size) {
    const float* logits    = (const float*)d_in[0];
    const float* embed     = (const float*)d_in[1];
    const float* centers   = (const float*)d_in[2];
    const float* queue     = (const float*)d_in[3];
    const float* prior     = (const float*)d_in[4];
    const int*   targets   = (const int*)d_in[5];
    const unsigned char* cinit = (const unsigned char*)d_in[6];
    const int*   qlabels   = (const int*)d_in[7];
    float* out = (float*)d_out;

    __nv_bfloat16* featbf; cudaGetSymbolAddress((void**)&featbf, g_featbf);
    __nv_bfloat16* centbf; cudaGetSymbolAddress((void**)&centbf, g_centbf);
    __nv_bfloat16* qpbf;   cudaGetSymbolAddress((void**)&qpbf,   g_qpbf);
    __nv_bfloat16* Sbf;    cudaGetSymbolAddress((void**)&Sbf,    g_Sbf);
    float* CS; cudaGetSymbolAddress((void**)&CS, g_CS);

    cudaFuncSetAttribute(gemm_dual, cudaFuncAttributeMaxDynamicSharedMemorySize, SMEM_GEMM);

    norm_rows_bf<<<BATCH, 128>>>(embed, featbf);
    norm_rows_bf<<<NCLS, 128>>>(centers, centbf);
    build_perm<<<1, 1024>>>(qlabels);
    permute_queue_bf<<<(QSZ * 128) / 256, 256>>>(queue);

    dim3 gD(QTILES + CTILES, BATCH / TBM);   // 72 x 32
    gemm_dual<<<gD, 256, SMEM_GEMM>>>(featbf, qpbf, centbf, Sbf, CS);

    row_both<<<BATCH, 256>>>(logits, prior, targets, cinit);
    finalize<<<1, 1>>>(out);
}

// round 17
// speedup vs baseline: 1.2510x; 1.0875x over previous
#include <cuda_runtime.h>
#include <cuda_bf16.h>
#include <math.h>
#include <stdint.h>

#define BATCH 4096
#define NCLS 1000
#define DIM 512
#define QSZ 8192
#define INV_T (1.0f / 0.07f)
#define EPSP 1e-8f

// ---------------- scratch (__device__ globals; no allocations allowed) ------
__device__ __nv_bfloat16 g_featbf[BATCH * DIM];   // normalized embeddings (bf16)
__device__ __nv_bfloat16 g_centbf[NCLS * DIM];    // normalized centers (bf16)
__device__ __nv_bfloat16 g_qpbf[QSZ * DIM];       // label-permuted queue (bf16)
__device__ __nv_bfloat16 g_Sbf[(size_t)BATCH * QSZ];  // feat @ queue_p^T / T (bf16)
__device__ float g_CS[(size_t)BATCH * NCLS];      // feat @ cent^T / T
__device__ int   g_start[NCLS + 2];
__device__ int   g_perm[QSZ];
__device__ double g_acc[2];
__device__ int   g_ctr;

// ---------------- fused row L2 normalize (embed + centers) -> bf16 -----------
__global__ void norm_all_bf(const float* __restrict__ embed,
                            const float* __restrict__ centers) {
    int r = blockIdx.x;
    const float* x;
    __nv_bfloat16* y;
    int row;
    if (r < BATCH) { x = embed;   y = g_featbf; row = r; }
    else           { x = centers; y = g_centbf; row = r - BATCH; }
    const float4* xr = (const float4*)(x + (size_t)row * DIM);
    float4 v = xr[threadIdx.x];
    float ss = v.x * v.x + v.y * v.y + v.z * v.z + v.w * v.w;
#pragma unroll
    for (int o = 16; o; o >>= 1) ss += __shfl_down_sync(0xffffffffu, ss, o);
    __shared__ float sh[4];
    if ((threadIdx.x & 31) == 0) sh[threadIdx.x >> 5] = ss;
    __syncthreads();
    float tot = sh[0] + sh[1] + sh[2] + sh[3];
    float inv = 1.0f / fmaxf(sqrtf(tot), 1e-12f);
    __nv_bfloat162 lo = __floats2bfloat162_rn(v.x * inv, v.y * inv);
    __nv_bfloat162 hi = __floats2bfloat162_rn(v.z * inv, v.w * inv);
    __nv_bfloat162* yr = (__nv_bfloat162*)(y + (size_t)row * DIM);
    yr[threadIdx.x * 2 + 0] = lo;
    yr[threadIdx.x * 2 + 1] = hi;
}

// ---------------- counting sort (single block, parallel scan) ---------------
__global__ void build_perm(const int* __restrict__ labels) {
    __shared__ int cnt[1024];    // 1001 used, rest zero
    __shared__ int scan[1024];
    __shared__ int scur[1024];
    int tid = threadIdx.x;
    cnt[tid] = 0;
    if (tid == 0) { g_acc[0] = 0.0; g_acc[1] = 0.0; g_ctr = 0; }
    __syncthreads();
    for (int q = tid; q < QSZ; q += 1024) {
        int l = labels[q];
        int b = (l >= 0 && l < NCLS) ? l : NCLS;
        atomicAdd(&cnt[b], 1);
    }
    __syncthreads();
    // Hillis-Steele inclusive scan over 1024 elements
    int own = cnt[tid];
    scan[tid] = own;
    __syncthreads();
#pragma unroll
    for (int off = 1; off < 1024; off <<= 1) {
        int add = (tid >= off) ? scan[tid - off] : 0;
        __syncthreads();
        scan[tid] += add;
        __syncthreads();
    }
    int ex = scan[tid] - own;   // exclusive
    scur[tid] = ex;
    if (tid <= NCLS) g_start[tid] = ex;
    if (tid == NCLS) g_start[NCLS + 1] = scan[NCLS];
    __syncthreads();
    for (int q = tid; q < QSZ; q += 1024) {
        int l = labels[q];
        int b = (l >= 0 && l < NCLS) ? l : NCLS;
        int p = atomicAdd(&scur[b], 1);
        g_perm[p] = q;
    }
}

// ---------------- gather queue rows into label-sorted order (f32 -> bf16) ---
__global__ void permute_queue_bf(const float* __restrict__ queue) {
    int idx = blockIdx.x * blockDim.x + threadIdx.x;  // QSZ*128
    int r = idx >> 7, c = idx & 127;
    int src = g_perm[r];
    float4 v = ((const float4*)queue)[(size_t)src * 128 + c];
    __nv_bfloat162 lo = __floats2bfloat162_rn(v.x, v.y);
    __nv_bfloat162 hi = __floats2bfloat162_rn(v.z, v.w);
    __nv_bfloat162* yr = (__nv_bfloat162*)(g_qpbf + (size_t)r * DIM);
    yr[c * 2 + 0] = lo;
    yr[c * 2 + 1] = hi;
}

// ---------------- merged bf16 tensor-core GEMM (k64 tiles, 3-stage) ----------
// bx < QTILES: S = feat @ qp^T * INV_T   -> bf16 out [BATCH, QSZ]
// else:        CS = feat @ cent^T * INV_T -> f32 out [BATCH, NCLS] (guarded)
// Block 128x128x64, 8 warps (4 M x 2 N), 3-stage cp.async, 96 KB dyn smem.
// SMEM tile rows are 128 B (8 x 16B chunks); swizzle: chunk ^= (row & 7).
#define TBM 128
#define TBN 128
#define TBK 64
#define NSTG 3
#define QTILES (QSZ / TBN)              // 64
#define CTILES ((NCLS + TBN - 1) / TBN) // 8
#define STG_BYTES (TBM * 128)           // 16384 per matrix per stage
#define A_TOTAL (NSTG * STG_BYTES)      // 49152
#define SMEM_GEMM (2 * A_TOTAL)         // 98304

__device__ __forceinline__ uint32_t smem_u32(const void* p) {
    uint32_t a;
    asm("{ .reg .u64 t; cvta.to.shared.u64 t, %1; cvt.u32.u64 %0, t; }"
        : "=r"(a) : "l"(p));
    return a;
}

__device__ __forceinline__ void mma_bf16(float c[4], const uint32_t a[4], const uint32_t b[2]) {
    asm volatile(
        "mma.sync.aligned.m16n8k16.row.col.f32.bf16.bf16.f32 "
        "{%0,%1,%2,%3}, {%4,%5,%6,%7}, {%8,%9}, {%0,%1,%2,%3};"
        : "+f"(c[0]), "+f"(c[1]), "+f"(c[2]), "+f"(c[3])
        : "r"(a[0]), "r"(a[1]), "r"(a[2]), "r"(a[3]), "r"(b[0]), "r"(b[1]));
}

__device__ __forceinline__ void ldsm4(uint32_t& r0, uint32_t& r1, uint32_t& r2, uint32_t& r3,
                                      uint32_t addr) {
    asm volatile("ldmatrix.sync.aligned.m8n8.x4.shared.b16 {%0,%1,%2,%3}, [%4];"
                 : "=r"(r0), "=r"(r1), "=r"(r2), "=r"(r3) : "r"(addr));
}

__device__ __forceinline__ void cpa16(uint32_t dst, const void* src, bool valid) {
    asm volatile("cp.async.cg.shared.global [%0], [%1], 16, %2;"
                 :: "r"(dst), "l"(src), "r"(valid ? 16 : 0));
}
#define CPA_COMMIT() asm volatile("cp.async.commit_group;" ::: "memory")
#define CPA_WAIT1()  asm volatile("cp.async.wait_group 1;" ::: "memory")

__global__ __launch_bounds__(256, 2) void gemm_dual(const __nv_bfloat16* __restrict__ A,
                                                    const __nv_bfloat16* __restrict__ Bq,
                                                    const __nv_bfloat16* __restrict__ Bc,
                                                    __nv_bfloat16* __restrict__ Sout,
                                                    float* __restrict__ Cout) {
    extern __shared__ __align__(16) char dsm[];
    int tid = threadIdx.x;
    int bx = blockIdx.x, by = blockIdx.y;
    const float alpha = INV_T;
    const int K = DIM;

    bool isq = bx < QTILES;
    const __nv_bfloat16* Bm = isq ? Bq : Bc;
    int bxl = isq ? bx : bx - QTILES;
    int N = isq ? QSZ : NCLS;

    int wid = tid >> 5, lane = tid & 31;
    int g = lane >> 2, t = lane & 3;
    int wm = (wid & 3) * 32;       // warp offset along M
    int wn = (wid >> 2) * 64;      // warp offset along N

    // fill mapping: row r0 (+32p), 16B chunk ch8
    int r0 = tid >> 3;             // 0..31
    int ch8 = tid & 7;             // 0..7
    int sc = ch8 ^ (r0 & 7);       // swizzle (invariant under r0 += 32)
    uint32_t dOff = ((uint32_t)r0 * 8 + sc) * 16;

    uint32_t Abase = smem_u32(dsm);
    uint32_t Bbase = Abase + A_TOTAL;

    // ldmatrix per-lane invariants
    int l15 = lane & 15, hi = lane >> 4;
    int rowA = wm + l15;
    int rowB = wn + l15;

    float acc[2][8][4];
#pragma unroll
    for (int i = 0; i < 2; i++)
#pragma unroll
        for (int j = 0; j < 8; j++)
#pragma unroll
            for (int r = 0; r < 4; r++) acc[i][j][r] = 0.f;

    const __nv_bfloat16* srcA = A + (size_t)(by * TBM + r0) * K + ch8 * 8;
    int nrowb = bxl * TBN + r0;
    const __nv_bfloat16* srcB = Bm + (size_t)nrowb * K + ch8 * 8;
    bool bv[4];
#pragma unroll
    for (int p = 0; p < 4; p++) bv[p] = (nrowb + 32 * p) < N;
    const size_t rstep = (size_t)32 * K;

    const int ntiles = K / TBK;   // 8

    // prologue: issue stages 0..1
#pragma unroll
    for (int s = 0; s < NSTG - 1; s++) {
        uint32_t so = (uint32_t)s * STG_BYTES;
        int kc = s * TBK;
#pragma unroll
        for (int p = 0; p < 4; p++) {
            cpa16(Abase + so + dOff + p * 4096, srcA + p * rstep + kc, true);
            cpa16(Bbase + so + dOff + p * 4096, srcB + p * rstep + kc, bv[p]);
        }
        CPA_COMMIT();
    }

    int stg = 0, wstg = NSTG - 1;
    for (int kt = 0; kt < ntiles; kt++) {
        CPA_WAIT1();          // tile kt resident (this thread's part)
        __syncthreads();      // whole tile visible; all warps done with buf wstg

        if (kt + NSTG - 1 < ntiles) {
            uint32_t so = (uint32_t)wstg * STG_BYTES;
            int kc = (kt + NSTG - 1) * TBK;
#pragma unroll
            for (int p = 0; p < 4; p++) {
                cpa16(Abase + so + dOff + p * 4096, srcA + p * rstep + kc, true);
                cpa16(Bbase + so + dOff + p * 4096, srcB + p * rstep + kc, bv[p]);
            }
        }
        CPA_COMMIT();         // always commit (empty group in tail)

        uint32_t Ab = Abase + (uint32_t)stg * STG_BYTES;
        uint32_t Bb = Bbase + (uint32_t)stg * STG_BYTES;
#pragma unroll
        for (int ks = 0; ks < 4; ks++) {
            int cb = ks * 2 + hi;   // chunk before swizzle (0..7)
            uint32_t afr[2][4], bfr[8][2];
#pragma unroll
            for (int i = 0; i < 2; i++) {
                int r = rowA + i * 16;
                int c = cb ^ (r & 7);
                ldsm4(afr[i][0], afr[i][1], afr[i][2], afr[i][3],
                      Ab + (uint32_t)r * 128 + (uint32_t)c * 16);
            }
#pragma unroll
            for (int jj = 0; jj < 4; jj++) {
                int r = rowB + jj * 16;
                int c = cb ^ (r & 7);
                uint32_t q0, q1, q2, q3;
                ldsm4(q0, q1, q2, q3, Bb + (uint32_t)r * 128 + (uint32_t)c * 16);
                bfr[2 * jj][0] = q0;  bfr[2 * jj][1] = q2;
                bfr[2 * jj + 1][0] = q1;  bfr[2 * jj + 1][1] = q3;
            }
#pragma unroll
            for (int i = 0; i < 2; i++)
#pragma unroll
                for (int j = 0; j < 8; j++) mma_bf16(acc[i][j], afr[i], bfr[j]);
        }
        stg = stg + 1; if (stg == NSTG) stg = 0;
        wstg = wstg + 1; if (wstg == NSTG) wstg = 0;
    }

#pragma unroll
    for (int i = 0; i < 2; i++) {
        int row = by * TBM + wm + i * 16 + g;
#pragma unroll
        for (int j = 0; j < 8; j++) {
            int col = bxl * TBN + wn + j * 8 + t * 2;
            if (isq) {
                __nv_bfloat162 v0 = __floats2bfloat162_rn(alpha * acc[i][j][0],
                                                          alpha * acc[i][j][1]);
                __nv_bfloat162 v1 = __floats2bfloat162_rn(alpha * acc[i][j][2],
                                                          alpha * acc[i][j][3]);
                *(__nv_bfloat162*)(Sout + (size_t)row * QSZ + col) = v0;
                *(__nv_bfloat162*)(Sout + (size_t)(row + 8) * QSZ + col) = v1;
            } else {
                if (col + 1 < NCLS) {
                    float2 v0 = make_float2(alpha * acc[i][j][0], alpha * acc[i][j][1]);
                    float2 v1 = make_float2(alpha * acc[i][j][2], alpha * acc[i][j][3]);
                    *(float2*)(Cout + (size_t)row * NCLS + col) = v0;
                    *(float2*)(Cout + (size_t)(row + 8) * NCLS + col) = v1;
                } else if (col < NCLS) {
                    Cout[(size_t)row * NCLS + col] = alpha * acc[i][j][0];
                    Cout[(size_t)(row + 8) * NCLS + col] = alpha * acc[i][j][2];
                }
            }
        }
    }
}

// ---------------- fused CE: both loss terms + final reduction ----------------
__global__ __launch_bounds__(256) void row_both(const float* __restrict__ logits,
                                                const float* __restrict__ prior,
                                                const int* __restrict__ targets,
                                                const unsigned char* __restrict__ init,
                                                float* __restrict__ out) {
    int b = blockIdx.x, tid = threadIdx.x;
    __shared__ __nv_bfloat16 sS[QSZ];          // 16 KB
    __shared__ float sm1[256], ss1[256], sm2[256], ss2[256];
    __shared__ float stv1, stv2;

    const uint4* src = (const uint4*)(g_Sbf + (size_t)b * QSZ);
    uint4* dst = (uint4*)sS;
#pragma unroll
    for (int i = 0; i < 4; i++) dst[tid + i * 256] = src[tid + i * 256];

    const float* CSrow = g_CS + (size_t)b * NCLS;
    const float* Lrow = logits + (size_t)b * NCLS;
    int tgt = targets[b];
    __syncthreads();

    float m1 = -INFINITY, s1 = 0.f;   // contrastive
    float m2 = -INFINITY, s2 = 0.f;   // cls
    for (int c = tid; c < NCLS; c += 256) {
        float pa = logf(fmaxf(prior[c], EPSP));
        int q0 = g_start[c], q1 = g_start[c + 1];
        int cnt = q1 - q0;
        float ql = 0.f;
        if (cnt > 0) {
            float mx = -INFINITY;
            for (int q = q0; q < q1; q++) mx = fmaxf(mx, __bfloat162float(sS[q]));
            float se = 0.f;
            for (int q = q0; q < q1; q++) se += __expf(__bfloat162float(sS[q]) - mx);
            ql = mx + __logf(se) - __logf((float)cnt);
        }
        float cl = init[c] ? CSrow[c] : 0.f;
        float a = fmaxf(cl, ql), d = fminf(cl, ql);
        float v1 = a + log1pf(__expf(d - a)) - pa;
        float v2 = Lrow[c] - pa;
        if (c == tgt) { stv1 = v1; stv2 = v2; }
        if (v1 > m1) { s1 = s1 * __expf(m1 - v1) + 1.f; m1 = v1; }
        else          { s1 += __expf(v1 - m1); }
        if (v2 > m2) { s2 = s2 * __expf(m2 - v2) + 1.f; m2 = v2; }
        else          { s2 += __expf(v2 - m2); }
    }
    sm1[tid] = m1; ss1[tid] = s1;
    sm2[tid] = m2; ss2[tid] = s2;
    __syncthreads();
    for (int o = 128; o; o >>= 1) {
        if (tid < o) {
            float ma = sm1[tid + o], sa = ss1[tid + o];
            float M = fmaxf(sm1[tid], ma);
            ss1[tid] = ss1[tid] * __expf(sm1[tid] - M) + sa * __expf(ma - M);
            sm1[tid] = M;
            float mb = sm2[tid + o], sb = ss2[tid + o];
            float M2 = fmaxf(sm2[tid], mb);
            ss2[tid] = ss2[tid] * __expf(sm2[tid] - M2) + sb * __expf(mb - M2);
            sm2[tid] = M2;
        }
        __syncthreads();
    }
    if (tid == 0) {
        float lse1 = sm1[0] + __logf(ss1[0]);
        float lse2 = sm2[0] + __logf(ss2[0]);
        atomicAdd(&g_acc[1], (double)(lse1 - stv1));
        atomicAdd(&g_acc[0], (double)(lse2 - stv2));
        __threadfence();
        int old = atomicAdd(&g_ctr, 1);
        if (old == BATCH - 1) {
            double a0 = *((volatile double*)&g_acc[0]);
            double a1 = *((volatile double*)&g_acc[1]);
            out[0] = (float)(1.0 * (a0 / BATCH) + 0.1 * (a1 / BATCH));
        }
    }
}

// ---------------- launch ----------------------------------------------------
extern "C" void kernel_launch(void* const* d_in, const int* in_sizes, int n_in,
                              void* d_out, int out_size) {
    const float* logits    = (const float*)d_in[0];
    const float* embed     = (const float*)d_in[1];
    const float* centers   = (const float*)d_in[2];
    const float* queue     = (const float*)d_in[3];
    const float* prior     = (const float*)d_in[4];
    const int*   targets   = (const int*)d_in[5];
    const unsigned char* cinit = (const unsigned char*)d_in[6];
    const int*   qlabels   = (const int*)d_in[7];
    float* out = (float*)d_out;

    __nv_bfloat16* featbf; cudaGetSymbolAddress((void**)&featbf, g_featbf);
    __nv_bfloat16* centbf; cudaGetSymbolAddress((void**)&centbf, g_centbf);
    __nv_bfloat16* qpbf;   cudaGetSymbolAddress((void**)&qpbf,   g_qpbf);
    __nv_bfloat16* Sbf;    cudaGetSymbolAddress((void**)&Sbf,    g_Sbf);
    float* CS; cudaGetSymbolAddress((void**)&CS, g_CS);

    cudaFuncSetAttribute(gemm_dual, cudaFuncAttributeMaxDynamicSharedMemorySize, SMEM_GEMM);

    norm_all_bf<<<BATCH + NCLS, 128>>>(embed, centers);
    build_perm<<<1, 1024>>>(qlabels);
    permute_queue_bf<<<(QSZ * 128) / 256, 256>>>(queue);

    dim3 gD(QTILES + CTILES, BATCH / TBM);   // 72 x 32
    gemm_dual<<<gD, 256, SMEM_GEMM>>>(featbf, qpbf, centbf, Sbf, CS);

    row_both<<<BATCH, 256>>>(logits, prior, targets, cinit, out);
}